// round 12
// baseline (speedup 1.0000x reference)
#include <cuda_runtime.h>

#define FULLMASK 0xffffffffu
#define NTAGS 32
#define BOS_IDX 30
#define EOS_IDX 31
#define L2E 1.4426950408889634f
#define LN2 0.6931471805599453f

typedef unsigned long long ull;

static __device__ __forceinline__ void ffma2(ull& d, ull a, ull b) {
    asm("fma.rn.f32x2 %0, %1, %2, %0;" : "+l"(d) : "l"(a), "l"(b));
}
static __device__ __forceinline__ float ex2_(float x) {
    float r; asm("ex2.approx.f32 %0, %1;" : "=f"(r) : "f"(x)); return r;
}
static __device__ __forceinline__ float lg2_(float x) {
    float r; asm("lg2.approx.f32 %0, %1;" : "=f"(r) : "f"(x)); return r;
}
static __device__ __forceinline__ float hsum1(ull a) {
    float x, y;
    asm("mov.b64 {%0,%1}, %2;" : "=f"(x), "=f"(y) : "l"(a));
    return x + y;
}
static __device__ __forceinline__ ull pack2(float x, float y) {
    ull r;
    asm("mov.b64 %0, {%1,%2};" : "=l"(r) : "f"(x), "f"(y));
    return r;
}

// ---------------------------------------------------------------------------
// One warp per sequence, lane = tag.  Multiplicative recurrence in log2 domain
// (R4/R8/R11-verified numerics), rescaled every 2nd step (R11-verified):
//   s_j = sum_i G[j,i]*beta_i;  beta' = s*K;  K = ex2(em*L2E [- D])
//   D = lg2(s_EOS captured on the previous (odd) step); Csum += D.
// Exchange is PURE SHFL (no smem in the loop): lane l gathers its quarter of
// betas (lanes c0..c0+7, c0 = 8*((l>>3)&3)) with 8 shfl.idx, computes quarter
// dots for rows {l, l^8, l^16, l^24}, and combines partials across lane
// groups:  Q0 = P0 + xor8(P1);  Q1 = P2 + xor8(P3);  s = Q0 + xor16(Q1).
// This removes the STS->LDS round-trip (LSU commit latency) from the serial
// chain entirely.
// ---------------------------------------------------------------------------

struct StepState { float beta, Cs, sE; };

template <bool RESCALE>
static __device__ __forceinline__ void crf_step(
    StepState& st, float emt, int c0,
    const ull* e0, const ull* e1, const ull* e2, const ull* e3)
{
    float K;
    if (RESCALE) {
        float D = lg2_(st.sE);
        st.Cs += D;
        K = ex2_(fmaf(emt, L2E, -D));
    } else {
        K = ex2_(emt * L2E);
    }

    // gather this lane's 8-beta quarter via shfl.idx (independent, pipelined)
    float b0 = __shfl_sync(FULLMASK, st.beta, c0 + 0);
    float b1 = __shfl_sync(FULLMASK, st.beta, c0 + 1);
    float b2 = __shfl_sync(FULLMASK, st.beta, c0 + 2);
    float b3 = __shfl_sync(FULLMASK, st.beta, c0 + 3);
    float b4 = __shfl_sync(FULLMASK, st.beta, c0 + 4);
    float b5 = __shfl_sync(FULLMASK, st.beta, c0 + 5);
    float b6 = __shfl_sync(FULLMASK, st.beta, c0 + 6);
    float b7 = __shfl_sync(FULLMASK, st.beta, c0 + 7);
    ull p0 = pack2(b0, b1);
    ull p1 = pack2(b2, b3);
    ull p2 = pack2(b4, b5);
    ull p3 = pack2(b6, b7);

    // quarter dots: one packed accumulator per row
    ull A0 = 0ull, A1 = 0ull, A2 = 0ull, A3 = 0ull;
    ffma2(A0, e0[0], p0); ffma2(A1, e1[0], p0);
    ffma2(A2, e2[0], p0); ffma2(A3, e3[0], p0);
    ffma2(A0, e0[1], p1); ffma2(A1, e1[1], p1);
    ffma2(A2, e2[1], p1); ffma2(A3, e3[1], p1);
    ffma2(A0, e0[2], p2); ffma2(A1, e1[2], p2);
    ffma2(A2, e2[2], p2); ffma2(A3, e3[2], p2);
    ffma2(A0, e0[3], p3); ffma2(A1, e1[3], p3);
    ffma2(A2, e2[3], p3); ffma2(A3, e3[3], p3);

    float P0 = hsum1(A0);                      // row l,    my quarter
    float P1 = hsum1(A1);                      // row l^8,  my quarter
    float P2 = hsum1(A2);                      // row l^16, my quarter
    float P3 = hsum1(A3);                      // row l^24, my quarter

    float Q0 = P0 + __shfl_xor_sync(FULLMASK, P1, 8);
    float Q1 = P2 + __shfl_xor_sync(FULLMASK, P3, 8);
    float s  = Q0 + __shfl_xor_sync(FULLMASK, Q1, 16);

    if (!RESCALE)  // capture anchor on non-rescale (odd) steps, lag-1
        st.sE = __shfl_sync(FULLMASK, s, EOS_IDX);
    st.beta = s * K;
}

__global__ __launch_bounds__(64, 1) void crf_forward_kernel(
    const float* __restrict__ emission,   // [B, T, 32]
    const float* __restrict__ trans,      // [32, 32]
    float* __restrict__ out,              // [B]
    int B, int T)
{
    const int lane = threadIdx.x & 31;
    const int w    = threadIdx.x >> 5;
    const int b    = blockIdx.x * 2 + w;

    if (b >= B) return;  // warp-uniform

    // G quarter-rows for this lane: rows {l, l^8, l^16, l^24} over this lane's
    // column group c0..c0+7, packed f32x2.
    const int c0 = 8 * ((lane >> 3) & 3);
    ull e0[4], e1[4], e2[4], e3[4];
    {
        const int r0 = lane, r1 = lane ^ 8, r2 = lane ^ 16, r3 = lane ^ 24;
        #pragma unroll
        for (int p = 0; p < 4; p++) {
            e0[p] = pack2(expf(trans[r0 * NTAGS + c0 + 2 * p]),
                          expf(trans[r0 * NTAGS + c0 + 2 * p + 1]));
            e1[p] = pack2(expf(trans[r1 * NTAGS + c0 + 2 * p]),
                          expf(trans[r1 * NTAGS + c0 + 2 * p + 1]));
            e2[p] = pack2(expf(trans[r2 * NTAGS + c0 + 2 * p]),
                          expf(trans[r2 * NTAGS + c0 + 2 * p + 1]));
            e3[p] = pack2(expf(trans[r3 * NTAGS + c0 + 2 * p]),
                          expf(trans[r3 * NTAGS + c0 + 2 * p + 1]));
        }
    }

    const float* em = emission + (size_t)b * T * NTAGS + lane;

    // step 0 analytic (only BOS survives init alpha), log2 units, EOS-anchored
    StepState st;
    {
        float a2 = (em[0] + trans[lane * NTAGS + BOS_IDX]) * L2E;
        st.Cs = __shfl_sync(FULLMASK, a2, EOS_IDX);
        st.beta = ex2_(a2 - st.Cs);          // 0 on dead BOS lane
        st.sE = 1.0f;
    }

    // emission prefetch ring, depth 4 (off-chain)
    float ring[4];
    #pragma unroll
    for (int i = 0; i < 4; i++) {
        int tt = (i + 1 < T) ? (i + 1) : (T - 1);
        ring[i] = em[(size_t)tt * NTAGS];
    }

    // steps in (odd, even) pairs: odd captures sE, even rescales with it
    int t = 1;
    #pragma unroll 2
    for (; t + 1 < T; t += 2) {
        float ea = ring[0], eb = ring[1];
        ring[0] = ring[2]; ring[1] = ring[3];
        int tp0 = (t + 4 < T) ? (t + 4) : (T - 1);
        int tp1 = (t + 5 < T) ? (t + 5) : (T - 1);
        ring[2] = em[(size_t)tp0 * NTAGS];
        ring[3] = em[(size_t)tp1 * NTAGS];

        crf_step<false>(st, ea, c0, e0, e1, e2, e3);
        crf_step<true>(st, eb, c0, e0, e1, e2, e3);
    }
    if (t < T)
        crf_step<false>(st, ring[0], c0, e0, e1, e2, e3);

    // materialize alpha (log2 units) and terminal lse over the warp
    float ahat = lg2_(st.beta) + st.Cs;             // -inf on BOS lane: ok
    float v = fmaf(trans[EOS_IDX * NTAGS + lane], L2E, ahat);
    float mm = v;
    #pragma unroll
    for (int o = 16; o; o >>= 1)
        mm = fmaxf(mm, __shfl_xor_sync(FULLMASK, mm, o));
    float ex = ex2_(v - mm);
    #pragma unroll
    for (int o = 16; o; o >>= 1)
        ex += __shfl_xor_sync(FULLMASK, ex, o);
    if (lane == 0)
        out[b] = (mm + lg2_(ex)) * LN2;
}

extern "C" void kernel_launch(void* const* d_in, const int* in_sizes, int n_in,
                              void* d_out, int out_size)
{
    const float* em = (const float*)d_in[0];
    const float* tr = (const float*)d_in[1];
    long long em_elems = in_sizes[0];
    if (n_in >= 2 && in_sizes[0] == NTAGS * NTAGS && in_sizes[1] > NTAGS * NTAGS) {
        em = (const float*)d_in[1];
        tr = (const float*)d_in[0];
        em_elems = in_sizes[1];
    }

    int B = out_size;
    int T = (int)(em_elems / ((long long)B * NTAGS));

    int blocks = (B + 1) / 2;  // 2 warps (2 sequences) per 64-thread CTA
    crf_forward_kernel<<<blocks, 64>>>(em, tr, (float*)d_out, B, T);
}

// round 13
// speedup vs baseline: 1.2332x; 1.2332x over previous
#include <cuda_runtime.h>

#define FULLMASK 0xffffffffu
#define NTAGS 32
#define BOS_IDX 30
#define EOS_IDX 31
#define L2E 1.4426950408889634f
#define LN2 0.6931471805599453f

typedef unsigned long long ull;

static __device__ __forceinline__ void ffma2(ull& d, ull a, ull b) {
    asm("fma.rn.f32x2 %0, %1, %2, %0;" : "+l"(d) : "l"(a), "l"(b));
}
static __device__ __forceinline__ ull add2(ull a, ull b) {
    ull r; asm("add.rn.f32x2 %0, %1, %2;" : "=l"(r) : "l"(a), "l"(b)); return r;
}
static __device__ __forceinline__ float ex2_(float x) {
    float r; asm("ex2.approx.f32 %0, %1;" : "=f"(r) : "f"(x)); return r;
}
static __device__ __forceinline__ float lg2_(float x) {
    float r; asm("lg2.approx.f32 %0, %1;" : "=f"(r) : "f"(x)); return r;
}
static __device__ __forceinline__ ull pack2(float x, float y) {
    ull r; asm("mov.b64 %0, {%1,%2};" : "=l"(r) : "f"(x), "f"(y)); return r;
}
static __device__ __forceinline__ void unpack2(ull v, float& x, float& y) {
    asm("mov.b64 {%0,%1}, %2;" : "=f"(x), "=f"(y) : "l"(v));
}

// ---------------------------------------------------------------------------
// 2 sequences per warp, packed (seq0,seq1) in 64-bit words; fwd/bwd split
// (R9/R10-verified math).  Multiplicative lag-1 recurrence in log2 domain,
// rescaled every 2nd step (R11/R12-verified).
// Exchange: STS.64 of packed beta into a 16-line swizzled layout
//   tp = tag>>1, phys = ((tp&7)<<1)|(tp>>3)
// so read k (k=0..7) is ONE contiguous 32B span (lanes 0-15 read line 2k,
// lanes 16-31 line 2k+1) = 1 wavefront; each u64 lane of the LDS.128 is one
// tag's (b0,b1) pair, feeding packed-pair FFMA2 with duplicated-G operands:
//   acc_row = sum_c (G[r,c],G[r,c]) * (b0_c,b1_c)   -> (s0_r, s1_r), no hsum.
// Combine: one xor16 level (lane l has rows l and l^16 over its half).
// No __syncwarp (convergent lanes, in-order LSU; R5/R6/R8-verified).
// ---------------------------------------------------------------------------

struct PState {
    ull  beta;            // packed (beta_seq0, beta_seq1)
    float Cs0, Cs1;       // accumulated log2 constants
    float sE0, sE1;       // lag anchors
};

template <bool RESCALE, bool BWD>
static __device__ __forceinline__ void crf_step(
    PState& st, float e0, float e1, unsigned stA, unsigned ldA,
    const ull* g0, const ull* g1, int anchor)
{
    float K0, K1;
    if (RESCALE) {
        float D0 = lg2_(st.sE0);
        float D1 = lg2_(st.sE1);
        st.Cs0 += D0; st.Cs1 += D1;
        K0 = ex2_(fmaf(e0, L2E, -D0));
        K1 = ex2_(fmaf(e1, L2E, -D1));
    } else {
        K0 = ex2_(e0 * L2E);
        K1 = ex2_(e1 * L2E);
    }

    ull x;
    if (BWD) {                       // pre-multiply (backward)
        float b0, b1; unpack2(st.beta, b0, b1);
        x = pack2(b0 * K0, b1 * K1);
    } else {
        x = st.beta;
    }

    asm volatile("st.shared.b64 [%0], %1;" :: "r"(stA), "l"(x) : "memory");

    // 8x LDS.128, each = tags (16h'+2k, 16h'+2k+1) as two (b0,b1) u64 words
    ull A0 = 0ull, A1 = 0ull, B0 = 0ull, B1 = 0ull;
    #pragma unroll
    for (int k = 0; k < 8; k++) {
        ull pl, ph;
        asm volatile("ld.shared.v2.u64 {%0,%1}, [%2];"
                     : "=l"(pl), "=l"(ph) : "r"(ldA + k * 32));
        ffma2(A0, g0[2 * k],     pl);
        ffma2(A1, g0[2 * k + 1], ph);
        ffma2(B0, g1[2 * k],     pl);
        ffma2(B1, g1[2 * k + 1], ph);
    }
    ull A = add2(A0, A1);            // row 'lane',    my half: (s0,s1) partial
    ull Bp = add2(B0, B1);           // row 'lane^16', my half

    float a0, a1, w0, w1;
    unpack2(A, a0, a1);
    unpack2(Bp, w0, w1);
    float s0 = a0 + __shfl_xor_sync(FULLMASK, w0, 16);
    float s1 = a1 + __shfl_xor_sync(FULLMASK, w1, 16);

    if (!RESCALE) {                  // capture anchors (lag-1)
        st.sE0 = __shfl_sync(FULLMASK, s0, anchor);
        st.sE1 = __shfl_sync(FULLMASK, s1, anchor);
    }
    if (BWD)
        st.beta = pack2(s0, s1);
    else
        st.beta = pack2(s0 * K0, s1 * K1);   // post-multiply (forward)
}

__global__ __launch_bounds__(128, 1) void crf_fb2_kernel(
    const float* __restrict__ emission,   // [B, T, 32]
    const float* __restrict__ trans,      // [32, 32]
    float* __restrict__ out,              // [B]
    int B, int T)
{
    const int lane = threadIdx.x & 31;
    const int wid  = threadIdx.x >> 5;    // 0..3
    const int pair = wid >> 1;            // which seq-pair in this CTA
    const int dir  = wid & 1;             // 0 = forward, 1 = backward
    const int b0   = blockIdx.x * 4 + pair * 2;
    const int b1   = b0 + 1;

    // exchange: per warp 2 buffers x 256B (16 swizzled 16B lines)
    __shared__ __align__(16) char sexc[4][2][256];
    __shared__ float sfin[2][2][2][NTAGS];   // [pair][dir][seq][tag]
    __shared__ float scst[2][2][2];          // [pair][dir][seq]

    // duplicated-G half rows: rows (lane, lane^16) over cols 16h'..16h'+15;
    // backward uses G^T (columns of G).
    const int hp = lane >> 4;              // 0 or 1: which tag-half we read
    const int r0 = lane, r1 = lane ^ 16;
    ull g0[16], g1[16];
    #pragma unroll
    for (int j = 0; j < 16; j++) {
        int c = 16 * hp + j;
        float x = (dir == 0) ? expf(trans[r0 * NTAGS + c])
                             : expf(trans[c * NTAGS + r0]);
        float y = (dir == 0) ? expf(trans[r1 * NTAGS + c])
                             : expf(trans[c * NTAGS + r1]);
        g0[j] = pack2(x, x);
        g1[j] = pack2(y, y);
    }

    const float* em0 = emission + (size_t)b0 * T * NTAGS + lane;
    const float* em1 = emission + (size_t)b1 * T * NTAGS + lane;
    const int M = (T - 1) >> 1;            // fwd: steps 1..M; bwd: T-1..M+1

    // swizzled addresses: store tp=lane>>1, phys=((tp&7)<<1)|(tp>>3)
    const unsigned sa = (unsigned)__cvta_generic_to_shared(&sexc[wid][0][0]);
    const int tp = lane >> 1;
    const unsigned stBase = sa + (unsigned)((((tp & 7) << 1) | (tp >> 3)) * 16
                                            + (lane & 1) * 8);
    const unsigned ldBase = sa + (unsigned)(hp * 16);
    unsigned stA = stBase, ldA = ldBase;   // toggled by XOR 256

    PState st;
    int anchor;
    if (dir == 0) {
        // forward init: step 0 analytic, EOS-anchored, log2 units
        float tb = trans[lane * NTAGS + BOS_IDX];
        float a20 = (em0[0] + tb) * L2E;
        float a21 = (em1[0] + tb) * L2E;
        st.Cs0 = __shfl_sync(FULLMASK, a20, EOS_IDX);
        st.Cs1 = __shfl_sync(FULLMASK, a21, EOS_IDX);
        st.beta = pack2(ex2_(a20 - st.Cs0), ex2_(a21 - st.Cs1));
        st.sE0 = 1.0f; st.sE1 = 1.0f;
        anchor = EOS_IDX;

        float ra[4], rb[4];
        #pragma unroll
        for (int i = 0; i < 4; i++) {
            int tt = (i + 1 < T) ? (i + 1) : (T - 1);
            ra[i] = em0[(size_t)tt * NTAGS];
            rb[i] = em1[(size_t)tt * NTAGS];
        }

        int t = 1;
        #pragma unroll 2
        for (; t + 1 <= M; t += 2) {
            float ea0 = ra[0], eb0 = rb[0], ea1 = ra[1], eb1 = rb[1];
            ra[0] = ra[2]; ra[1] = ra[3]; rb[0] = rb[2]; rb[1] = rb[3];
            int q0 = (t + 4 < T) ? (t + 4) : (T - 1);
            int q1 = (t + 5 < T) ? (t + 5) : (T - 1);
            ra[2] = em0[(size_t)q0 * NTAGS]; ra[3] = em0[(size_t)q1 * NTAGS];
            rb[2] = em1[(size_t)q0 * NTAGS]; rb[3] = em1[(size_t)q1 * NTAGS];

            stA ^= 256u; ldA ^= 256u;
            crf_step<false, false>(st, ea0, eb0, stA, ldA, g0, g1, anchor);
            stA ^= 256u; ldA ^= 256u;
            crf_step<true, false>(st, ea1, eb1, stA, ldA, g0, g1, anchor);
        }
        if (t <= M) {
            stA ^= 256u; ldA ^= 256u;
            crf_step<false, false>(st, ra[0], rb[0], stA, ldA, g0, g1, anchor);
        }
    } else {
        // backward init: v = exp(trans[EOS,:]) (v_EOS = 0), both seqs equal
        float v0 = expf(trans[EOS_IDX * NTAGS + lane]);
        st.beta = pack2(v0, v0);
        st.Cs0 = 0.0f; st.Cs1 = 0.0f;
        st.sE0 = 1.0f; st.sE1 = 1.0f;
        anchor = 0;
        int nb = T - 1 - M;                // emissions T-1 down to M+1

        float ra[4], rb[4];
        #pragma unroll
        for (int i = 0; i < 4; i++) {
            int tt = T - 1 - i; if (tt < 0) tt = 0;
            ra[i] = em0[(size_t)tt * NTAGS];
            rb[i] = em1[(size_t)tt * NTAGS];
        }

        int i = 0;
        #pragma unroll 2
        for (; i + 1 < nb; i += 2) {
            float ea0 = ra[0], eb0 = rb[0], ea1 = ra[1], eb1 = rb[1];
            ra[0] = ra[2]; ra[1] = ra[3]; rb[0] = rb[2]; rb[1] = rb[3];
            int q0 = T - 1 - i - 4; if (q0 < 0) q0 = 0;
            int q1 = T - 1 - i - 5; if (q1 < 0) q1 = 0;
            ra[2] = em0[(size_t)q0 * NTAGS]; ra[3] = em0[(size_t)q1 * NTAGS];
            rb[2] = em1[(size_t)q0 * NTAGS]; rb[3] = em1[(size_t)q1 * NTAGS];

            stA ^= 256u; ldA ^= 256u;
            crf_step<false, true>(st, ea0, eb0, stA, ldA, g0, g1, anchor);
            stA ^= 256u; ldA ^= 256u;
            crf_step<true, true>(st, ea1, eb1, stA, ldA, g0, g1, anchor);
        }
        if (i < nb) {
            stA ^= 256u; ldA ^= 256u;
            crf_step<false, true>(st, ra[0], rb[0], stA, ldA, g0, g1, anchor);
        }
    }

    // join: Z_seq = sum_j beta_fwd,j * v_bwd,j ; log Z = (lg2 + Cf + Cb) ln2
    {
        float f0, f1; unpack2(st.beta, f0, f1);
        sfin[pair][dir][0][lane] = f0;
        sfin[pair][dir][1][lane] = f1;
        if (lane == 0) {
            scst[pair][dir][0] = st.Cs0;
            scst[pair][dir][1] = st.Cs1;
        }
    }
    __syncthreads();

    if (dir == 0) {
        #pragma unroll
        for (int s = 0; s < 2; s++) {
            float p = sfin[pair][0][s][lane] * sfin[pair][1][s][lane];
            #pragma unroll
            for (int o = 16; o; o >>= 1)
                p += __shfl_xor_sync(FULLMASK, p, o);
            if (lane == 0 && b0 + s < B)
                out[b0 + s] = (lg2_(p) + scst[pair][0][s] + scst[pair][1][s])
                              * LN2;
        }
    }
}

extern "C" void kernel_launch(void* const* d_in, const int* in_sizes, int n_in,
                              void* d_out, int out_size)
{
    const float* em = (const float*)d_in[0];
    const float* tr = (const float*)d_in[1];
    long long em_elems = in_sizes[0];
    if (n_in >= 2 && in_sizes[0] == NTAGS * NTAGS && in_sizes[1] > NTAGS * NTAGS) {
        em = (const float*)d_in[1];
        tr = (const float*)d_in[0];
        em_elems = in_sizes[1];
    }

    int B = out_size;
    int T = (int)(em_elems / ((long long)B * NTAGS));

    // 128 threads = 4 warps: {fwd,bwd} x {2 seq-pairs}; 4 sequences per CTA
    int blocks = (B + 3) / 4;
    crf_fb2_kernel<<<blocks, 128>>>(em, tr, (float*)d_out, B, T);
}

// round 14
// speedup vs baseline: 1.2501x; 1.0137x over previous
#include <cuda_runtime.h>

#define FULLMASK 0xffffffffu
#define NTAGS 32
#define BOS_IDX 30
#define EOS_IDX 31
#define L2E 1.4426950408889634f
#define LN2 0.6931471805599453f

typedef unsigned long long ull;

static __device__ __forceinline__ void ffma2(ull& d, ull a, ull b) {
    asm("fma.rn.f32x2 %0, %1, %2, %0;" : "+l"(d) : "l"(a), "l"(b));
}
static __device__ __forceinline__ ull add2(ull a, ull b) {
    ull r; asm("add.rn.f32x2 %0, %1, %2;" : "=l"(r) : "l"(a), "l"(b)); return r;
}
static __device__ __forceinline__ ull mul2(ull a, ull b) {
    ull r; asm("mul.rn.f32x2 %0, %1, %2;" : "=l"(r) : "l"(a), "l"(b)); return r;
}
static __device__ __forceinline__ float ex2_(float x) {
    float r; asm("ex2.approx.f32 %0, %1;" : "=f"(r) : "f"(x)); return r;
}
static __device__ __forceinline__ float lg2_(float x) {
    float r; asm("lg2.approx.f32 %0, %1;" : "=f"(r) : "f"(x)); return r;
}
static __device__ __forceinline__ ull pack2(float x, float y) {
    ull r; asm("mov.b64 %0, {%1,%2};" : "=l"(r) : "f"(x), "f"(y)); return r;
}
static __device__ __forceinline__ void unpack2(ull v, float& x, float& y) {
    asm("mov.b64 {%0,%1}, %2;" : "=f"(x), "=f"(y) : "l"(v));
}
static __device__ __forceinline__ ull shxor2(ull v, int m) {
    float a, b; unpack2(v, a, b);
    return pack2(__shfl_xor_sync(FULLMASK, a, m),
                 __shfl_xor_sync(FULLMASK, b, m));
}

// ---------------------------------------------------------------------------
// 2 sequences per warp packed (seq0,seq1) in u64; fwd/bwd split (R9/R13-
// verified).  Multiplicative lag-1 log2 recurrence, rescale every 2nd step
// (R11/R12/R13-verified).
// QUARTER-split exchange (R11-verified scheme), packed:
//   lane l owns quarter q=(l>>3)&3, cols c0=8q; computes rows {l,l^8,l^16,l^24}
//   combine: Q0 = A0 + xor8(A1); Q1 = A2 + xor8(A3); S = Q0 + xor16(Q1)
// Permuted chunk-major smem layout: tag t at ((t&7)>>1)*64 + (t>>3)*16 +
// (t&1)*8, so each of 4 LDS.128 reads one contiguous 64B span (1 wavefront)
// and each lane pulls only 64B/step (halves smem return bandwidth vs R13).
// No __syncwarp (convergent lanes, in-order LSU; R5/R6/R8-verified).
// ---------------------------------------------------------------------------

struct PState {
    ull  beta;            // packed (beta_seq0, beta_seq1)
    float Cs0, Cs1;       // accumulated log2 constants
    float sE0, sE1;       // lag anchors
};

template <bool RESCALE, bool BWD>
static __device__ __forceinline__ void crf_step(
    PState& st, float e0, float e1, unsigned stA, unsigned ldq,
    const ull g[4][8], int anchor)
{
    float K0, K1;
    if (RESCALE) {
        float D0 = lg2_(st.sE0);
        float D1 = lg2_(st.sE1);
        st.Cs0 += D0; st.Cs1 += D1;
        K0 = ex2_(fmaf(e0, L2E, -D0));
        K1 = ex2_(fmaf(e1, L2E, -D1));
    } else {
        K0 = ex2_(e0 * L2E);
        K1 = ex2_(e1 * L2E);
    }
    ull Kp = pack2(K0, K1);

    ull x = BWD ? mul2(st.beta, Kp) : st.beta;   // bwd pre-multiplies
    asm volatile("st.shared.b64 [%0], %1;" :: "r"(stA), "l"(x) : "memory");

    // 4x LDS.128, each one 64B-contiguous across the warp (1 wavefront):
    // load j gives tags (c0+2j, c0+2j+1) as two packed-pair u64 words.
    ull A0 = 0ull, A1 = 0ull, A2 = 0ull, A3 = 0ull;
    #pragma unroll
    for (int j = 0; j < 4; j++) {
        ull pl, ph;
        asm volatile("ld.shared.v2.u64 {%0,%1}, [%2];"
                     : "=l"(pl), "=l"(ph) : "r"(ldq + j * 64));
        ffma2(A0, g[0][2 * j], pl); ffma2(A0, g[0][2 * j + 1], ph);
        ffma2(A1, g[1][2 * j], pl); ffma2(A1, g[1][2 * j + 1], ph);
        ffma2(A2, g[2][2 * j], pl); ffma2(A2, g[2][2 * j + 1], ph);
        ffma2(A3, g[3][2 * j], pl); ffma2(A3, g[3][2 * j + 1], ph);
    }

    // combine partials across lane groups (packed; 6 shfl, 3 add2)
    ull Q0 = add2(A0, shxor2(A1, 8));
    ull Q1 = add2(A2, shxor2(A3, 8));
    ull S  = add2(Q0, shxor2(Q1, 16));

    if (!RESCALE) {                  // capture anchors (lag-1)
        float s0, s1; unpack2(S, s0, s1);
        st.sE0 = __shfl_sync(FULLMASK, s0, anchor);
        st.sE1 = __shfl_sync(FULLMASK, s1, anchor);
    }
    st.beta = BWD ? S : mul2(S, Kp);             // fwd post-multiplies
}

__global__ __launch_bounds__(128, 1) void crf_fb2_kernel(
    const float* __restrict__ emission,   // [B, T, 32]
    const float* __restrict__ trans,      // [32, 32]
    float* __restrict__ out,              // [B]
    int B, int T)
{
    const int lane = threadIdx.x & 31;
    const int wid  = threadIdx.x >> 5;    // 0..3
    const int pair = wid >> 1;            // which seq-pair in this CTA
    const int dir  = wid & 1;             // 0 = forward, 1 = backward
    const int b0   = blockIdx.x * 4 + pair * 2;
    const int b1   = b0 + 1;

    __shared__ __align__(16) char sexc[4][2][256];   // per-warp double buffer
    __shared__ float sfin[2][2][2][NTAGS];   // [pair][dir][seq][tag]
    __shared__ float scst[2][2][2];          // [pair][dir][seq]

    // quarter rows for this lane: rows {l, l^8, l^16, l^24} over cols
    // c0..c0+7, duplicated-packed; backward uses G^T (columns of G).
    const int c0 = 8 * ((lane >> 3) & 3);
    const int rows[4] = { lane, lane ^ 8, lane ^ 16, lane ^ 24 };
    ull g[4][8];
    #pragma unroll
    for (int r = 0; r < 4; r++) {
        #pragma unroll
        for (int k = 0; k < 8; k++) {
            int c = c0 + k;
            float v = (dir == 0) ? expf(trans[rows[r] * NTAGS + c])
                                 : expf(trans[c * NTAGS + rows[r]]);
            g[r][k] = pack2(v, v);
        }
    }

    const float* em0 = emission + (size_t)b0 * T * NTAGS + lane;
    const float* em1 = emission + (size_t)b1 * T * NTAGS + lane;
    const int M = (T - 1) >> 1;            // fwd: steps 1..M; bwd: T-1..M+1

    // permuted chunk-major addresses
    const unsigned sa = (unsigned)__cvta_generic_to_shared(&sexc[wid][0][0]);
    const unsigned stBase = sa + (unsigned)((((lane & 7) >> 1) * 64)
                                  + ((lane >> 3) * 16) + ((lane & 1) * 8));
    const unsigned ldBase = sa + (unsigned)(((lane >> 3) & 3) * 16);
    unsigned stA = stBase, ldq = ldBase;   // toggled by XOR 256

    PState st;
    int anchor;
    if (dir == 0) {
        // forward init: step 0 analytic, EOS-anchored, log2 units
        float tb = trans[lane * NTAGS + BOS_IDX];
        float a20 = (em0[0] + tb) * L2E;
        float a21 = (em1[0] + tb) * L2E;
        st.Cs0 = __shfl_sync(FULLMASK, a20, EOS_IDX);
        st.Cs1 = __shfl_sync(FULLMASK, a21, EOS_IDX);
        st.beta = pack2(ex2_(a20 - st.Cs0), ex2_(a21 - st.Cs1));
        st.sE0 = 1.0f; st.sE1 = 1.0f;
        anchor = EOS_IDX;

        float ra[4], rb[4];
        #pragma unroll
        for (int i = 0; i < 4; i++) {
            int tt = (i + 1 < T) ? (i + 1) : (T - 1);
            ra[i] = em0[(size_t)tt * NTAGS];
            rb[i] = em1[(size_t)tt * NTAGS];
        }

        int t = 1;
        #pragma unroll 2
        for (; t + 1 <= M; t += 2) {
            float ea0 = ra[0], eb0 = rb[0], ea1 = ra[1], eb1 = rb[1];
            ra[0] = ra[2]; ra[1] = ra[3]; rb[0] = rb[2]; rb[1] = rb[3];
            int q0 = (t + 4 < T) ? (t + 4) : (T - 1);
            int q1 = (t + 5 < T) ? (t + 5) : (T - 1);
            ra[2] = em0[(size_t)q0 * NTAGS]; ra[3] = em0[(size_t)q1 * NTAGS];
            rb[2] = em1[(size_t)q0 * NTAGS]; rb[3] = em1[(size_t)q1 * NTAGS];

            stA ^= 256u; ldq ^= 256u;
            crf_step<false, false>(st, ea0, eb0, stA, ldq, g, anchor);
            stA ^= 256u; ldq ^= 256u;
            crf_step<true, false>(st, ea1, eb1, stA, ldq, g, anchor);
        }
        if (t <= M) {
            stA ^= 256u; ldq ^= 256u;
            crf_step<false, false>(st, ra[0], rb[0], stA, ldq, g, anchor);
        }
    } else {
        // backward init: v = exp(trans[EOS,:]) (v_EOS = 0), both seqs equal
        float v0 = expf(trans[EOS_IDX * NTAGS + lane]);
        st.beta = pack2(v0, v0);
        st.Cs0 = 0.0f; st.Cs1 = 0.0f;
        st.sE0 = 1.0f; st.sE1 = 1.0f;
        anchor = 0;
        int nb = T - 1 - M;                // emissions T-1 down to M+1

        float ra[4], rb[4];
        #pragma unroll
        for (int i = 0; i < 4; i++) {
            int tt = T - 1 - i; if (tt < 0) tt = 0;
            ra[i] = em0[(size_t)tt * NTAGS];
            rb[i] = em1[(size_t)tt * NTAGS];
        }

        int i = 0;
        #pragma unroll 2
        for (; i + 1 < nb; i += 2) {
            float ea0 = ra[0], eb0 = rb[0], ea1 = ra[1], eb1 = rb[1];
            ra[0] = ra[2]; ra[1] = ra[3]; rb[0] = rb[2]; rb[1] = rb[3];
            int q0 = T - 1 - i - 4; if (q0 < 0) q0 = 0;
            int q1 = T - 1 - i - 5; if (q1 < 0) q1 = 0;
            ra[2] = em0[(size_t)q0 * NTAGS]; ra[3] = em0[(size_t)q1 * NTAGS];
            rb[2] = em1[(size_t)q0 * NTAGS]; rb[3] = em1[(size_t)q1 * NTAGS];

            stA ^= 256u; ldq ^= 256u;
            crf_step<false, true>(st, ea0, eb0, stA, ldq, g, anchor);
            stA ^= 256u; ldq ^= 256u;
            crf_step<true, true>(st, ea1, eb1, stA, ldq, g, anchor);
        }
        if (i < nb) {
            stA ^= 256u; ldq ^= 256u;
            crf_step<false, true>(st, ra[0], rb[0], stA, ldq, g, anchor);
        }
    }

    // join: Z_seq = sum_j beta_fwd,j * v_bwd,j ; log Z = (lg2 + Cf + Cb) ln2
    {
        float f0, f1; unpack2(st.beta, f0, f1);
        sfin[pair][dir][0][lane] = f0;
        sfin[pair][dir][1][lane] = f1;
        if (lane == 0) {
            scst[pair][dir][0] = st.Cs0;
            scst[pair][dir][1] = st.Cs1;
        }
    }
    __syncthreads();

    if (dir == 0) {
        #pragma unroll
        for (int s = 0; s < 2; s++) {
            float p = sfin[pair][0][s][lane] * sfin[pair][1][s][lane];
            #pragma unroll
            for (int o = 16; o; o >>= 1)
                p += __shfl_xor_sync(FULLMASK, p, o);
            if (lane == 0 && b0 + s < B)
                out[b0 + s] = (lg2_(p) + scst[pair][0][s] + scst[pair][1][s])
                              * LN2;
        }
    }
}

extern "C" void kernel_launch(void* const* d_in, const int* in_sizes, int n_in,
                              void* d_out, int out_size)
{
    const float* em = (const float*)d_in[0];
    const float* tr = (const float*)d_in[1];
    long long em_elems = in_sizes[0];
    if (n_in >= 2 && in_sizes[0] == NTAGS * NTAGS && in_sizes[1] > NTAGS * NTAGS) {
        em = (const float*)d_in[1];
        tr = (const float*)d_in[0];
        em_elems = in_sizes[1];
    }

    int B = out_size;
    int T = (int)(em_elems / ((long long)B * NTAGS));

    // 128 threads = 4 warps: {fwd,bwd} x {2 seq-pairs}; 4 sequences per CTA
    int blocks = (B + 3) / 4;
    crf_fb2_kernel<<<blocks, 128>>>(em, tr, (float*)d_out, B, T);
}

// round 15
// speedup vs baseline: 1.2754x; 1.0203x over previous
#include <cuda_runtime.h>

#define FULLMASK 0xffffffffu
#define NTAGS 32
#define BOS_IDX 30
#define EOS_IDX 31
#define L2E 1.4426950408889634f
#define LN2 0.6931471805599453f

typedef unsigned long long ull;

static __device__ __forceinline__ void ffma2(ull& d, ull a, ull b) {
    asm("fma.rn.f32x2 %0, %1, %2, %0;" : "+l"(d) : "l"(a), "l"(b));
}
static __device__ __forceinline__ ull add2(ull a, ull b) {
    ull r; asm("add.rn.f32x2 %0, %1, %2;" : "=l"(r) : "l"(a), "l"(b)); return r;
}
static __device__ __forceinline__ ull mul2(ull a, ull b) {
    ull r; asm("mul.rn.f32x2 %0, %1, %2;" : "=l"(r) : "l"(a), "l"(b)); return r;
}
static __device__ __forceinline__ float ex2_(float x) {
    float r; asm("ex2.approx.f32 %0, %1;" : "=f"(r) : "f"(x)); return r;
}
static __device__ __forceinline__ float lg2_(float x) {
    float r; asm("lg2.approx.f32 %0, %1;" : "=f"(r) : "f"(x)); return r;
}
static __device__ __forceinline__ ull pack2(float x, float y) {
    ull r; asm("mov.b64 %0, {%1,%2};" : "=l"(r) : "f"(x), "f"(y)); return r;
}
static __device__ __forceinline__ void unpack2(ull v, float& x, float& y) {
    asm("mov.b64 {%0,%1}, %2;" : "=f"(x), "=f"(y) : "l"(v));
}
static __device__ __forceinline__ ull shxor2(ull v, int m) {
    float a, b; unpack2(v, a, b);
    return pack2(__shfl_xor_sync(FULLMASK, a, m),
                 __shfl_xor_sync(FULLMASK, b, m));
}

// ---------------------------------------------------------------------------
// 2 sequences per warp packed (seq0,seq1) in u64; fwd/bwd split (R9/R13/R14-
// verified).  Multiplicative lag-1 log2 recurrence, rescale every 2nd step
// (R11..R14-verified).
// PURE-SHFL quarter exchange (no LSU in the loop): lane l gathers tag l^j for
// j=1..7 via packed shfl_xor (its own group's 8 betas, lane-permuted column
// order; G coefficients indexed col = l^j).  Accumulators per row
// {l, l^8, l^16, l^24}; combine (bit-identical to R14's verified scheme):
//   Q0 = A0 + xor8(A1); Q1 = A2 + xor8(A3); S = Q0 + xor16(Q1).
// ---------------------------------------------------------------------------

struct PState {
    ull  beta;            // packed (beta_seq0, beta_seq1)
    float Cs0, Cs1;       // accumulated log2 constants
    float sE0, sE1;       // lag anchors
};

template <bool RESCALE, bool BWD>
static __device__ __forceinline__ void crf_step(
    PState& st, float e0, float e1, const ull g[4][8], int anchor)
{
    float K0, K1;
    if (RESCALE) {
        float D0 = lg2_(st.sE0);
        float D1 = lg2_(st.sE1);
        st.Cs0 += D0; st.Cs1 += D1;
        K0 = ex2_(fmaf(e0, L2E, -D0));
        K1 = ex2_(fmaf(e1, L2E, -D1));
    } else {
        K0 = ex2_(e0 * L2E);
        K1 = ex2_(e1 * L2E);
    }
    ull Kp = pack2(K0, K1);
    ull x = BWD ? mul2(st.beta, Kp) : st.beta;   // bwd pre-multiplies

    // quarter dots via xor-gather: slot j holds tag l^j (group(l) betas)
    ull A0 = 0ull, A1 = 0ull, A2 = 0ull, A3 = 0ull;
    ffma2(A0, g[0][0], x); ffma2(A1, g[1][0], x);
    ffma2(A2, g[2][0], x); ffma2(A3, g[3][0], x);
    #pragma unroll
    for (int j = 1; j < 8; j++) {
        ull bj = shxor2(x, j);
        ffma2(A0, g[0][j], bj); ffma2(A1, g[1][j], bj);
        ffma2(A2, g[2][j], bj); ffma2(A3, g[3][j], bj);
    }

    // combine partials across lane groups (R14-verified; packed)
    ull Q0 = add2(A0, shxor2(A1, 8));
    ull Q1 = add2(A2, shxor2(A3, 8));
    ull S  = add2(Q0, shxor2(Q1, 16));

    if (!RESCALE) {                  // capture anchors (lag-1)
        float s0, s1; unpack2(S, s0, s1);
        st.sE0 = __shfl_sync(FULLMASK, s0, anchor);
        st.sE1 = __shfl_sync(FULLMASK, s1, anchor);
    }
    st.beta = BWD ? S : mul2(S, Kp);             // fwd post-multiplies
}

__global__ __launch_bounds__(128, 1) void crf_fb2_kernel(
    const float* __restrict__ emission,   // [B, T, 32]
    const float* __restrict__ trans,      // [32, 32]
    float* __restrict__ out,              // [B]
    int B, int T)
{
    const int lane = threadIdx.x & 31;
    const int wid  = threadIdx.x >> 5;    // 0..3
    const int pair = wid >> 1;            // which seq-pair in this CTA
    const int dir  = wid & 1;             // 0 = forward, 1 = backward
    const int b0   = blockIdx.x * 4 + pair * 2;
    const int b1   = b0 + 1;

    __shared__ float sfin[2][2][2][NTAGS];   // [pair][dir][seq][tag]
    __shared__ float scst[2][2][2];          // [pair][dir][seq]

    // G coefficients for this lane: rows {l, l^8, l^16, l^24}, gather slot j
    // holds column l^j (j=0..7); duplicated-packed. Backward uses G^T.
    const int rows[4] = { lane, lane ^ 8, lane ^ 16, lane ^ 24 };
    ull g[4][8];
    #pragma unroll
    for (int r = 0; r < 4; r++) {
        #pragma unroll
        for (int j = 0; j < 8; j++) {
            int c = lane ^ j;              // stays within group(lane)
            float v = (dir == 0) ? expf(trans[rows[r] * NTAGS + c])
                                 : expf(trans[c * NTAGS + rows[r]]);
            g[r][j] = pack2(v, v);
        }
    }

    const float* em0 = emission + (size_t)b0 * T * NTAGS + lane;
    const float* em1 = emission + (size_t)b1 * T * NTAGS + lane;
    const int M = (T - 1) >> 1;            // fwd: steps 1..M; bwd: T-1..M+1

    PState st;
    int anchor;
    if (dir == 0) {
        // forward init: step 0 analytic, EOS-anchored, log2 units
        float tb = trans[lane * NTAGS + BOS_IDX];
        float a20 = (em0[0] + tb) * L2E;
        float a21 = (em1[0] + tb) * L2E;
        st.Cs0 = __shfl_sync(FULLMASK, a20, EOS_IDX);
        st.Cs1 = __shfl_sync(FULLMASK, a21, EOS_IDX);
        st.beta = pack2(ex2_(a20 - st.Cs0), ex2_(a21 - st.Cs1));
        st.sE0 = 1.0f; st.sE1 = 1.0f;
        anchor = EOS_IDX;

        float ra[4], rb[4];
        #pragma unroll
        for (int i = 0; i < 4; i++) {
            int tt = (i + 1 < T) ? (i + 1) : (T - 1);
            ra[i] = em0[(size_t)tt * NTAGS];
            rb[i] = em1[(size_t)tt * NTAGS];
        }

        int t = 1;
        #pragma unroll 2
        for (; t + 1 <= M; t += 2) {
            float ea0 = ra[0], eb0 = rb[0], ea1 = ra[1], eb1 = rb[1];
            ra[0] = ra[2]; ra[1] = ra[3]; rb[0] = rb[2]; rb[1] = rb[3];
            int q0 = (t + 4 < T) ? (t + 4) : (T - 1);
            int q1 = (t + 5 < T) ? (t + 5) : (T - 1);
            ra[2] = em0[(size_t)q0 * NTAGS]; ra[3] = em0[(size_t)q1 * NTAGS];
            rb[2] = em1[(size_t)q0 * NTAGS]; rb[3] = em1[(size_t)q1 * NTAGS];

            crf_step<false, false>(st, ea0, eb0, g, anchor);
            crf_step<true,  false>(st, ea1, eb1, g, anchor);
        }
        if (t <= M)
            crf_step<false, false>(st, ra[0], rb[0], g, anchor);
    } else {
        // backward init: v = exp(trans[EOS,:]) (v_EOS = 0), both seqs equal
        float v0 = expf(trans[EOS_IDX * NTAGS + lane]);
        st.beta = pack2(v0, v0);
        st.Cs0 = 0.0f; st.Cs1 = 0.0f;
        st.sE0 = 1.0f; st.sE1 = 1.0f;
        anchor = 0;
        int nb = T - 1 - M;                // emissions T-1 down to M+1

        float ra[4], rb[4];
        #pragma unroll
        for (int i = 0; i < 4; i++) {
            int tt = T - 1 - i; if (tt < 0) tt = 0;
            ra[i] = em0[(size_t)tt * NTAGS];
            rb[i] = em1[(size_t)tt * NTAGS];
        }

        int i = 0;
        #pragma unroll 2
        for (; i + 1 < nb; i += 2) {
            float ea0 = ra[0], eb0 = rb[0], ea1 = ra[1], eb1 = rb[1];
            ra[0] = ra[2]; ra[1] = ra[3]; rb[0] = rb[2]; rb[1] = rb[3];
            int q0 = T - 1 - i - 4; if (q0 < 0) q0 = 0;
            int q1 = T - 1 - i - 5; if (q1 < 0) q1 = 0;
            ra[2] = em0[(size_t)q0 * NTAGS]; ra[3] = em0[(size_t)q1 * NTAGS];
            rb[2] = em1[(size_t)q0 * NTAGS]; rb[3] = em1[(size_t)q1 * NTAGS];

            crf_step<false, true>(st, ea0, eb0, g, anchor);
            crf_step<true,  true>(st, ea1, eb1, g, anchor);
        }
        if (i < nb)
            crf_step<false, true>(st, ra[0], rb[0], g, anchor);
    }

    // join: Z_seq = sum_j beta_fwd,j * v_bwd,j ; log Z = (lg2 + Cf + Cb) ln2
    {
        float f0, f1; unpack2(st.beta, f0, f1);
        sfin[pair][dir][0][lane] = f0;
        sfin[pair][dir][1][lane] = f1;
        if (lane == 0) {
            scst[pair][dir][0] = st.Cs0;
            scst[pair][dir][1] = st.Cs1;
        }
    }
    __syncthreads();

    if (dir == 0) {
        #pragma unroll
        for (int s = 0; s < 2; s++) {
            float p = sfin[pair][0][s][lane] * sfin[pair][1][s][lane];
            #pragma unroll
            for (int o = 16; o; o >>= 1)
                p += __shfl_xor_sync(FULLMASK, p, o);
            if (lane == 0 && b0 + s < B)
                out[b0 + s] = (lg2_(p) + scst[pair][0][s] + scst[pair][1][s])
                              * LN2;
        }
    }
}

extern "C" void kernel_launch(void* const* d_in, const int* in_sizes, int n_in,
                              void* d_out, int out_size)
{
    const float* em = (const float*)d_in[0];
    const float* tr = (const float*)d_in[1];
    long long em_elems = in_sizes[0];
    if (n_in >= 2 && in_sizes[0] == NTAGS * NTAGS && in_sizes[1] > NTAGS * NTAGS) {
        em = (const float*)d_in[1];
        tr = (const float*)d_in[0];
        em_elems = in_sizes[1];
    }

    int B = out_size;
    int T = (int)(em_elems / ((long long)B * NTAGS));

    // 128 threads = 4 warps: {fwd,bwd} x {2 seq-pairs}; 4 sequences per CTA
    int blocks = (B + 3) / 4;
    crf_fb2_kernel<<<blocks, 128>>>(em, tr, (float*)d_out, B, T);
}